// round 8
// baseline (speedup 1.0000x reference)
#include <cuda_runtime.h>

#define BATCH 8
#define CH 3
#define H 1024
#define W 1280
#define HW (H * W)
#define EPS 1e-7f
#define MIN_DEPTH 10.0f
#define MAX_DEPTH 255.0f

#define TILE_W 128
#define TILE_H 8
#define RPT 4                 // rows per thread

// Per-batch fused parameters: M (9 floats) + c (3 floats)
__device__ float g_MC[BATCH * 12];

__global__ void setup_params_kernel(const float* __restrict__ srcK,
                                    const float* __restrict__ tgtK,
                                    const float* __restrict__ tvec) {
    int b = threadIdx.x;
    if (b >= BATCH) return;
    const float* S = srcK + b * 16;
    const float* T = tgtK + b * 16;
    const float* t = tvec + b * 3;

    float a00 = S[0], a01 = S[1], a02 = S[2];
    float a10 = S[4], a11 = S[5], a12 = S[6];
    float a20 = S[8], a21 = S[9], a22 = S[10];
    float det = a00 * (a11 * a22 - a12 * a21)
              - a01 * (a10 * a22 - a12 * a20)
              + a02 * (a10 * a21 - a11 * a20);
    float id = 1.0f / det;
    float i00 = (a11 * a22 - a12 * a21) * id;
    float i01 = (a02 * a21 - a01 * a22) * id;
    float i02 = (a01 * a12 - a02 * a11) * id;
    float i10 = (a12 * a20 - a10 * a22) * id;
    float i11 = (a00 * a22 - a02 * a20) * id;
    float i12 = (a02 * a10 - a00 * a12) * id;
    float i20 = (a10 * a21 - a11 * a20) * id;
    float i21 = (a01 * a20 - a00 * a21) * id;
    float i22 = (a00 * a11 - a01 * a10) * id;

    float k00 = T[0], k01 = T[1], k02 = T[2];
    float k10 = T[4], k11 = T[5], k12 = T[6];
    float k20 = T[8], k21 = T[9], k22 = T[10];

    float* P = g_MC + b * 12;
    P[0] = k00 * i00 + k01 * i10 + k02 * i20;
    P[1] = k00 * i01 + k01 * i11 + k02 * i21;
    P[2] = k00 * i02 + k01 * i12 + k02 * i22;
    P[3] = k10 * i00 + k11 * i10 + k12 * i20;
    P[4] = k10 * i01 + k11 * i11 + k12 * i21;
    P[5] = k10 * i02 + k11 * i12 + k12 * i22;
    P[6] = k20 * i00 + k21 * i10 + k22 * i20;
    P[7] = k20 * i01 + k21 * i11 + k22 * i21;
    P[8] = k20 * i02 + k21 * i12 + k22 * i22;
    P[9]  = k00 * t[0] + k01 * t[1] + k02 * t[2];
    P[10] = k10 * t[0] + k11 * t[1] + k12 * t[2];
    P[11] = k20 * t[0] + k21 * t[1] + k22 * t[2];
}

// grid: (W/TILE_W, H/TILE_H, BATCH), block 256 = 128 cols x 2 rows; RPT rows/thread.
// Phase-split with explicit register budget (min 2 blocks/SM -> up to 128 regs):
// all disp loads -> all coords -> all 48 gathers outstanding -> blend -> store.
__global__ __launch_bounds__(256, 2) void synth_kernel(const float* __restrict__ img,
                                                       const float* __restrict__ disp,
                                                       float* __restrict__ out) {
    __shared__ float sP[12];

    const int b  = blockIdx.z;
    const int yt = blockIdx.y * TILE_H;
    const int xt = blockIdx.x * TILE_W;
    const int tid = threadIdx.x;

    if (tid < 12) sP[tid] = g_MC[b * 12 + tid];
    __syncthreads();

    const float m0 = sP[0], m1 = sP[1], m2 = sP[2];
    const float m3 = sP[3], m4 = sP[4], m5 = sP[5];
    const float m6 = sP[6], m7 = sP[7], m8 = sP[8];
    const float c0 = sP[9], c1 = sP[10], c2 = sP[11];

    const int lx = tid & (TILE_W - 1);   // adjacent lanes -> adjacent x
    const int rp = tid >> 7;             // 0 or 1
    const int x  = xt + lx;
    const float fx = (float)x;

    const float tx_x = m0 * fx + m2;
    const float tx_y = m3 * fx + m5;
    const float tx_z = m6 * fx + m8;

    const float min_disp = 1.0f / MAX_DEPTH;
    const float max_disp = 1.0f / MIN_DEPTH;
    const float SXW = (float)W / (float)(W - 1);
    const float SYH = (float)H / (float)(H - 1);

    const float* dbase = disp + (size_t)b * HW;
    const float* imb   = img  + (size_t)b * CH * HW;
    float* outb        = out  + (size_t)b * CH * HW;

    const int gidx0 = (yt + rp) * W + x;

    // ---- Phase 1: all disp loads (independent) ----
    float dval[RPT];
#pragma unroll
    for (int k = 0; k < RPT; k++)
        dval[k] = __ldg(dbase + gidx0 + k * 2 * W);

    // ---- Phase 2: all coordinates / weights / tap base addresses ----
    const float* a00[RPT];
    int odx[RPT], ody[RPT];
    float w00[RPT], w01[RPT], w10[RPT], w11[RPT];
    const float fy0 = (float)(yt + rp);
    // incremental y-terms (step = 2 rows)
    float ay_x = m1 * fy0 + tx_x;  const float sy_x = 2.0f * m1;
    float ay_y = m4 * fy0 + tx_y;  const float sy_y = 2.0f * m4;
    float ay_z = m7 * fy0 + tx_z;  const float sy_z = 2.0f * m7;

#pragma unroll
    for (int k = 0; k < RPT; k++) {
        float depth = __fdividef(1.0f, min_disp + (max_disp - min_disp) * dval[k]);

        float cpx = depth * ay_x + c0;
        float cpy = depth * ay_y + c1;
        float cpz = depth * ay_z + c2;
        ay_x += sy_x; ay_y += sy_y; ay_z += sy_z;

        float inv_z = __fdividef(1.0f, cpz + EPS);
        float xf = (cpx * inv_z) * SXW - 0.5f;
        float yf = (cpy * inv_z) * SYH - 0.5f;

        int ix0 = __float2int_rd(xf);
        int iy0 = __float2int_rd(yf);
        float wx = xf - (float)ix0;
        float wy = yf - (float)iy0;

        int ix1 = min(max(ix0 + 1, 0), W - 1);
        int iy1 = min(max(iy0 + 1, 0), H - 1);
        ix0 = min(max(ix0, 0), W - 1);
        iy0 = min(max(iy0, 0), H - 1);

        float iwx = 1.0f - wx;
        float iwy = 1.0f - wy;
        w00[k] = iwx * iwy;
        w01[k] = wx * iwy;
        w10[k] = iwx * wy;
        w11[k] = wx * wy;

        a00[k] = imb + (iy0 * W + ix0);
        odx[k] = ix1 - ix0;              // 0 or 1
        ody[k] = (iy1 - iy0) * W;        // 0 or W
    }

    // ---- Phase 3: all 48 gathers (channel offsets folded as LDG immediates) ----
    float t00[RPT][CH], t01[RPT][CH], t10[RPT][CH], t11[RPT][CH];
#pragma unroll
    for (int k = 0; k < RPT; k++) {
        const float* p00 = a00[k];
        const float* p01 = p00 + odx[k];
        const float* p10 = p00 + ody[k];
        const float* p11 = p10 + odx[k];
#pragma unroll
        for (int ch = 0; ch < CH; ch++) {
            t00[k][ch] = __ldg(p00 + ch * HW);
            t01[k][ch] = __ldg(p01 + ch * HW);
            t10[k][ch] = __ldg(p10 + ch * HW);
            t11[k][ch] = __ldg(p11 + ch * HW);
        }
    }

    // ---- Phase 4: blend + store ----
#pragma unroll
    for (int k = 0; k < RPT; k++) {
        const int gidx = gidx0 + k * 2 * W;
#pragma unroll
        for (int ch = 0; ch < CH; ch++) {
            float v = t00[k][ch] * w00[k];
            v = fmaf(t01[k][ch], w01[k], v);
            v = fmaf(t10[k][ch], w10[k], v);
            v = fmaf(t11[k][ch], w11[k], v);
            outb[ch * HW + gidx] = v;
        }
    }
}

extern "C" void kernel_launch(void* const* d_in, const int* in_sizes, int n_in,
                              void* d_out, int out_size) {
    const float* img  = (const float*)d_in[0];
    const float* disp = (const float*)d_in[1];
    const float* srcK = (const float*)d_in[2];
    const float* tgtK = (const float*)d_in[3];
    const float* tvec = (const float*)d_in[4];
    float* out = (float*)d_out;

    setup_params_kernel<<<1, BATCH>>>(srcK, tgtK, tvec);
    dim3 grid(W / TILE_W, H / TILE_H, BATCH);   // (10, 128, 8)
    synth_kernel<<<grid, 256>>>(img, disp, out);
}

// round 9
// speedup vs baseline: 1.0134x; 1.0134x over previous
#include <cuda_runtime.h>

#define BATCH 8
#define CH 3
#define H 1024
#define W 1280
#define HW (H * W)
#define EPS 1e-7f
#define MIN_DEPTH 10.0f
#define MAX_DEPTH 255.0f

#define TILE_W 128
#define TILE_H 8
#define RPT 4                 // rows per thread

// Per-batch fused parameters: M (9 floats) + c (3 floats)
__device__ float g_MC[BATCH * 12];

__global__ void setup_params_kernel(const float* __restrict__ srcK,
                                    const float* __restrict__ tgtK,
                                    const float* __restrict__ tvec) {
    int b = threadIdx.x;
    if (b >= BATCH) return;
    const float* S = srcK + b * 16;
    const float* T = tgtK + b * 16;
    const float* t = tvec + b * 3;

    float a00 = S[0], a01 = S[1], a02 = S[2];
    float a10 = S[4], a11 = S[5], a12 = S[6];
    float a20 = S[8], a21 = S[9], a22 = S[10];
    float det = a00 * (a11 * a22 - a12 * a21)
              - a01 * (a10 * a22 - a12 * a20)
              + a02 * (a10 * a21 - a11 * a20);
    float id = 1.0f / det;
    float i00 = (a11 * a22 - a12 * a21) * id;
    float i01 = (a02 * a21 - a01 * a22) * id;
    float i02 = (a01 * a12 - a02 * a11) * id;
    float i10 = (a12 * a20 - a10 * a22) * id;
    float i11 = (a00 * a22 - a02 * a20) * id;
    float i12 = (a02 * a10 - a00 * a12) * id;
    float i20 = (a10 * a21 - a11 * a20) * id;
    float i21 = (a01 * a20 - a00 * a21) * id;
    float i22 = (a00 * a11 - a01 * a10) * id;

    float k00 = T[0], k01 = T[1], k02 = T[2];
    float k10 = T[4], k11 = T[5], k12 = T[6];
    float k20 = T[8], k21 = T[9], k22 = T[10];

    float* P = g_MC + b * 12;
    P[0] = k00 * i00 + k01 * i10 + k02 * i20;
    P[1] = k00 * i01 + k01 * i11 + k02 * i21;
    P[2] = k00 * i02 + k01 * i12 + k02 * i22;
    P[3] = k10 * i00 + k11 * i10 + k12 * i20;
    P[4] = k10 * i01 + k11 * i11 + k12 * i21;
    P[5] = k10 * i02 + k11 * i12 + k12 * i22;
    P[6] = k20 * i00 + k21 * i10 + k22 * i20;
    P[7] = k20 * i01 + k21 * i11 + k22 * i21;
    P[8] = k20 * i02 + k21 * i12 + k22 * i22;
    P[9]  = k00 * t[0] + k01 * t[1] + k02 * t[2];
    P[10] = k10 * t[0] + k11 * t[1] + k12 * t[2];
    P[11] = k20 * t[0] + k21 * t[1] + k22 * t[2];
}

// grid: (W/TILE_W, H/TILE_H, BATCH), block 256 = 128 cols x 2 rows; RPT rows/thread.
// Disp staged to shared (removes ~600cyc LDG from every iteration's chain).
// Interior blocks (79%) skip all border clamps.
template <bool INTERIOR>
__device__ __forceinline__ void synth_body(const float* __restrict__ img,
                                           float* __restrict__ out,
                                           const float* sDisp,
                                           const float* sP,
                                           int b, int yt, int xt, int tid) {
    const float m1 = sP[1], m4 = sP[4], m7 = sP[7];
    const float c0 = sP[9], c1 = sP[10], c2 = sP[11];

    const int lx = tid & (TILE_W - 1);
    const int rp = tid >> 7;             // 0 or 1
    const int x  = xt + lx;
    const float fx = (float)x;

    const float tx_x = sP[0] * fx + sP[2];
    const float tx_y = sP[3] * fx + sP[5];
    const float tx_z = sP[6] * fx + sP[8];

    const float min_disp = 1.0f / MAX_DEPTH;
    const float max_disp = 1.0f / MIN_DEPTH;
    const float SXW = (float)W / (float)(W - 1);
    const float SYH = (float)H / (float)(H - 1);

    const float* imb = img + (size_t)b * CH * HW;
    float* outb      = out + (size_t)b * CH * HW;

    const float fy0 = (float)(yt + rp);
    float ay_x = m1 * fy0 + tx_x;  const float sy_x = 2.0f * m1;
    float ay_y = m4 * fy0 + tx_y;  const float sy_y = 2.0f * m4;
    float ay_z = m7 * fy0 + tx_z;  const float sy_z = 2.0f * m7;

    int gidx = (yt + rp) * W + x;

#pragma unroll
    for (int k = 0; k < RPT; k++, gidx += 2 * W) {
        float d = sDisp[(rp + 2 * k) * TILE_W + lx];
        float depth = __fdividef(1.0f, min_disp + (max_disp - min_disp) * d);

        float cpx = depth * ay_x + c0;
        float cpy = depth * ay_y + c1;
        float cpz = depth * ay_z + c2;
        ay_x += sy_x; ay_y += sy_y; ay_z += sy_z;

        float inv_z = __fdividef(1.0f, cpz + EPS);
        float xf = (cpx * inv_z) * SXW - 0.5f;
        float yf = (cpy * inv_z) * SYH - 0.5f;

        int ix0 = __float2int_rd(xf);
        int iy0 = __float2int_rd(yf);
        float wx = xf - (float)ix0;
        float wy = yf - (float)iy0;

        int o00, dx, dyW;
        if (INTERIOR) {
            // bounds proven: ix0 in [x-1,x], iy0 in [y-1,y]; tile is interior
            o00 = iy0 * W + ix0;
            dx  = 1;
            dyW = W;
        } else {
            int ix1 = min(max(ix0 + 1, 0), W - 1);
            int iy1 = min(max(iy0 + 1, 0), H - 1);
            ix0 = min(max(ix0, 0), W - 1);
            iy0 = min(max(iy0, 0), H - 1);
            o00 = iy0 * W + ix0;
            dx  = ix1 - ix0;
            dyW = (iy1 - iy0) * W;
        }

        float iwx = 1.0f - wx;
        float iwy = 1.0f - wy;
        float w00 = iwx * iwy;
        float w01 = wx * iwy;
        float w10 = iwx * wy;
        float w11 = wx * wy;

        const float* p00 = imb + o00;
        const float* p01 = p00 + dx;
        const float* p10 = p00 + dyW;
        const float* p11 = p10 + dx;

        float t000 = __ldg(p00);            float t001 = __ldg(p00 + HW);
        float t002 = __ldg(p00 + 2 * HW);
        float t010 = __ldg(p01);            float t011 = __ldg(p01 + HW);
        float t012 = __ldg(p01 + 2 * HW);
        float t100 = __ldg(p10);            float t101 = __ldg(p10 + HW);
        float t102 = __ldg(p10 + 2 * HW);
        float t110 = __ldg(p11);            float t111 = __ldg(p11 + HW);
        float t112 = __ldg(p11 + 2 * HW);

        float v0 = t000 * w00;  v0 = fmaf(t010, w01, v0);
        v0 = fmaf(t100, w10, v0); v0 = fmaf(t110, w11, v0);
        float v1 = t001 * w00;  v1 = fmaf(t011, w01, v1);
        v1 = fmaf(t101, w10, v1); v1 = fmaf(t111, w11, v1);
        float v2 = t002 * w00;  v2 = fmaf(t012, w01, v2);
        v2 = fmaf(t102, w10, v2); v2 = fmaf(t112, w11, v2);

        outb[gidx]          = v0;
        outb[HW + gidx]     = v1;
        outb[2 * HW + gidx] = v2;
    }
}

__global__ __launch_bounds__(256) void synth_kernel(const float* __restrict__ img,
                                                    const float* __restrict__ disp,
                                                    float* __restrict__ out) {
    __shared__ float sP[12];
    __shared__ float sDisp[TILE_H * TILE_W];   // 4KB

    const int b  = blockIdx.z;
    const int yt = blockIdx.y * TILE_H;
    const int xt = blockIdx.x * TILE_W;
    const int tid = threadIdx.x;

    if (tid < 12) sP[tid] = g_MC[b * 12 + tid];

    // Stage all disp for the tile: 1 float4 per thread, coalesced.
    {
        const int idx = tid * 4;                 // 0..1020
        const int r = idx >> 7;                  // row in tile
        const int c = idx & (TILE_W - 1);        // col in tile
        const float4 dq = *(const float4*)(disp + (size_t)b * HW + (yt + r) * W + xt + c);
        *(float4*)(sDisp + idx) = dq;
    }
    __syncthreads();

    const bool interior = (blockIdx.x > 0) & (blockIdx.x < gridDim.x - 1)
                        & (blockIdx.y > 0) & (blockIdx.y < gridDim.y - 1);
    if (interior)
        synth_body<true>(img, out, sDisp, sP, b, yt, xt, tid);
    else
        synth_body<false>(img, out, sDisp, sP, b, yt, xt, tid);
}

extern "C" void kernel_launch(void* const* d_in, const int* in_sizes, int n_in,
                              void* d_out, int out_size) {
    const float* img  = (const float*)d_in[0];
    const float* disp = (const float*)d_in[1];
    const float* srcK = (const float*)d_in[2];
    const float* tgtK = (const float*)d_in[3];
    const float* tvec = (const float*)d_in[4];
    float* out = (float*)d_out;

    setup_params_kernel<<<1, BATCH>>>(srcK, tgtK, tvec);
    dim3 grid(W / TILE_W, H / TILE_H, BATCH);   // (10, 128, 8)
    synth_kernel<<<grid, 256>>>(img, disp, out);
}

// round 10
// speedup vs baseline: 1.1013x; 1.0867x over previous
#include <cuda_runtime.h>

#define BATCH 8
#define CH 3
#define H 1024
#define W 1280
#define HW (H * W)
#define EPS 1e-7f
#define MIN_DEPTH 10.0f
#define MAX_DEPTH 255.0f

#define TILE_W 128
#define TILE_H 8
#define RPT 4                 // rows per thread

// Phase-batched body (R6 structure, proven fastest). INTERIOR skips border clamps.
template <bool INTERIOR>
__device__ __forceinline__ void synth_body(const float* __restrict__ img,
                                           const float* __restrict__ disp,
                                           float* __restrict__ out,
                                           const float* sP,
                                           int b, int yt, int xt, int tid) {
    const float m1 = sP[1], m4 = sP[4], m7 = sP[7];
    const float c0 = sP[9], c1 = sP[10], c2 = sP[11];

    const int lx = tid & (TILE_W - 1);   // adjacent lanes -> adjacent x
    const int rp = tid >> 7;             // 0 or 1
    const int x  = xt + lx;
    const float fx = (float)x;

    const float tx_x = sP[0] * fx + sP[2];
    const float tx_y = sP[3] * fx + sP[5];
    const float tx_z = sP[6] * fx + sP[8];

    const float min_disp = 1.0f / MAX_DEPTH;
    const float max_disp = 1.0f / MIN_DEPTH;
    const float SXW = (float)W / (float)(W - 1);
    const float SYH = (float)H / (float)(H - 1);

    const float* dbase = disp + (size_t)b * HW;
    const float* imb   = img  + (size_t)b * CH * HW;
    float* outb        = out  + (size_t)b * CH * HW;

    const int gidx0 = (yt + rp) * W + x;

    // ---- Phase 1: all disp loads (independent, overlapped) ----
    float dval[RPT];
#pragma unroll
    for (int k = 0; k < RPT; k++)
        dval[k] = __ldg(dbase + gidx0 + k * 2 * W);

    // ---- Phase 2: all coordinates / weights / tap offsets ----
    int   o00[RPT], odx[RPT], ody[RPT];
    float w00[RPT], w01[RPT], w10[RPT], w11[RPT];
    const float fy0 = (float)(yt + rp);
    float ay_x = m1 * fy0 + tx_x;  const float sy_x = 2.0f * m1;
    float ay_y = m4 * fy0 + tx_y;  const float sy_y = 2.0f * m4;
    float ay_z = m7 * fy0 + tx_z;  const float sy_z = 2.0f * m7;

#pragma unroll
    for (int k = 0; k < RPT; k++) {
        float depth = __fdividef(1.0f, min_disp + (max_disp - min_disp) * dval[k]);

        float cpx = depth * ay_x + c0;
        float cpy = depth * ay_y + c1;
        float cpz = depth * ay_z + c2;
        ay_x += sy_x; ay_y += sy_y; ay_z += sy_z;

        float inv_z = __fdividef(1.0f, cpz + EPS);
        float xf = (cpx * inv_z) * SXW - 0.5f;
        float yf = (cpy * inv_z) * SYH - 0.5f;

        int ix0 = __float2int_rd(xf);
        int iy0 = __float2int_rd(yf);
        float wx = xf - (float)ix0;
        float wy = yf - (float)iy0;

        if (INTERIOR) {
            // warp-field bounds proven: ix0 in [x-1,x], iy0 in [y-1,y]; tile interior
            o00[k] = iy0 * W + ix0;
            odx[k] = 1;
            ody[k] = W;
        } else {
            int ix1 = min(max(ix0 + 1, 0), W - 1);
            int iy1 = min(max(iy0 + 1, 0), H - 1);
            ix0 = min(max(ix0, 0), W - 1);
            iy0 = min(max(iy0, 0), H - 1);
            o00[k] = iy0 * W + ix0;
            odx[k] = ix1 - ix0;
            ody[k] = (iy1 - iy0) * W;
        }

        float iwx = 1.0f - wx;
        float iwy = 1.0f - wy;
        w00[k] = iwx * iwy;
        w01[k] = wx * iwy;
        w10[k] = iwx * wy;
        w11[k] = wx * wy;
    }

    // ---- Phase 3: all gathers (channel offsets folded as LDG immediates) ----
    float t00[RPT][CH], t01[RPT][CH], t10[RPT][CH], t11[RPT][CH];
#pragma unroll
    for (int k = 0; k < RPT; k++) {
        const float* p00 = imb + o00[k];
        const float* p01 = p00 + odx[k];
        const float* p10 = p00 + ody[k];
        const float* p11 = p10 + odx[k];
#pragma unroll
        for (int ch = 0; ch < CH; ch++) {
            t00[k][ch] = __ldg(p00 + ch * HW);
            t01[k][ch] = __ldg(p01 + ch * HW);
            t10[k][ch] = __ldg(p10 + ch * HW);
            t11[k][ch] = __ldg(p11 + ch * HW);
        }
    }

    // ---- Phase 4: blend + store ----
#pragma unroll
    for (int k = 0; k < RPT; k++) {
        const int gidx = gidx0 + k * 2 * W;
#pragma unroll
        for (int ch = 0; ch < CH; ch++) {
            float v = t00[k][ch] * w00[k];
            v = fmaf(t01[k][ch], w01[k], v);
            v = fmaf(t10[k][ch], w10[k], v);
            v = fmaf(t11[k][ch], w11[k], v);
            outb[ch * HW + gidx] = v;
        }
    }
}

// Single fused kernel: lanes 0-11 compute fused projection params in-kernel.
__global__ __launch_bounds__(256) void synth_kernel(const float* __restrict__ img,
                                                    const float* __restrict__ disp,
                                                    const float* __restrict__ srcK,
                                                    const float* __restrict__ tgtK,
                                                    const float* __restrict__ tvec,
                                                    float* __restrict__ out) {
    __shared__ float sP[12];

    const int b  = blockIdx.z;
    const int yt = blockIdx.y * TILE_H;
    const int xt = blockIdx.x * TILE_W;
    const int tid = threadIdx.x;

    if (tid < 12) {
        const float* S = srcK + b * 16;
        const float* T = tgtK + b * 16;
        const float* t = tvec + b * 3;

        // adjugate of S[:3,:3] and determinant
        float a00 = __ldg(S + 0), a01 = __ldg(S + 1), a02 = __ldg(S + 2);
        float a10 = __ldg(S + 4), a11 = __ldg(S + 5), a12 = __ldg(S + 6);
        float a20 = __ldg(S + 8), a21 = __ldg(S + 9), a22 = __ldg(S + 10);
        float ad00 = a11 * a22 - a12 * a21;
        float ad01 = a02 * a21 - a01 * a22;
        float ad02 = a01 * a12 - a02 * a11;
        float ad10 = a12 * a20 - a10 * a22;
        float ad11 = a00 * a22 - a02 * a20;
        float ad12 = a02 * a10 - a00 * a12;
        float ad20 = a10 * a21 - a11 * a20;
        float ad21 = a01 * a20 - a00 * a21;
        float ad22 = a00 * a11 - a01 * a10;
        float id = 1.0f / (a00 * ad00 + a01 * ad10 + a02 * ad20);

        int r = (tid < 9) ? (tid / 3) : (tid - 9);
        float T0 = __ldg(T + r * 4 + 0);
        float T1 = __ldg(T + r * 4 + 1);
        float T2 = __ldg(T + r * 4 + 2);

        float val;
        if (tid < 9) {
            int c = tid - r * 3;
            float A0 = (c == 0) ? ad00 : (c == 1) ? ad01 : ad02;
            float A1 = (c == 0) ? ad10 : (c == 1) ? ad11 : ad12;
            float A2 = (c == 0) ? ad20 : (c == 1) ? ad21 : ad22;
            val = (T0 * A0 + T1 * A1 + T2 * A2) * id;
        } else {
            val = T0 * __ldg(t + 0) + T1 * __ldg(t + 1) + T2 * __ldg(t + 2);
        }
        sP[tid] = val;
    }
    __syncthreads();

    const bool interior = (blockIdx.x > 0) & (blockIdx.x < gridDim.x - 1)
                        & (blockIdx.y > 0) & (blockIdx.y < gridDim.y - 1);
    if (interior)
        synth_body<true>(img, disp, out, sP, b, yt, xt, tid);
    else
        synth_body<false>(img, disp, out, sP, b, yt, xt, tid);
}

extern "C" void kernel_launch(void* const* d_in, const int* in_sizes, int n_in,
                              void* d_out, int out_size) {
    const float* img  = (const float*)d_in[0];
    const float* disp = (const float*)d_in[1];
    const float* srcK = (const float*)d_in[2];
    const float* tgtK = (const float*)d_in[3];
    const float* tvec = (const float*)d_in[4];
    float* out = (float*)d_out;

    dim3 grid(W / TILE_W, H / TILE_H, BATCH);   // (10, 128, 8)
    synth_kernel<<<grid, 256>>>(img, disp, srcK, tgtK, tvec, out);
}

// round 11
// speedup vs baseline: 1.1275x; 1.0238x over previous
#include <cuda_runtime.h>

#define BATCH 8
#define CH 3
#define H 1024
#define W 1280
#define HW (H * W)
#define EPS 1e-7f
#define MIN_DEPTH 10.0f
#define MAX_DEPTH 255.0f

#define TILE_W 128
#define TILE_H 8
#define RPT 4                 // rows per thread

// Phase-batched body (R6 structure). Single-division projection:
//   pc = (M_s·p + c_s·s) / (az + (c2+eps)·s),  s = scaled_disp
// with grid-scale constants prefolded into M_s, c_s at param setup.
template <bool INTERIOR>
__device__ __forceinline__ void synth_body(const float* __restrict__ img,
                                           const float* __restrict__ disp,
                                           float* __restrict__ out,
                                           const float* sP,
                                           int b, int yt, int xt, int tid) {
    const float m1 = sP[1], m4 = sP[4], m7 = sP[7];
    const float c0 = sP[9], c1 = sP[10], c2e = sP[11];

    const int lx = tid & (TILE_W - 1);   // adjacent lanes -> adjacent x
    const int rp = tid >> 7;             // 0 or 1
    const int x  = xt + lx;
    const float fx = (float)x;

    const float tx_x = sP[0] * fx + sP[2];
    const float tx_y = sP[3] * fx + sP[5];
    const float tx_z = sP[6] * fx + sP[8];

    const float min_disp = 1.0f / MAX_DEPTH;
    const float drange   = 1.0f / MIN_DEPTH - 1.0f / MAX_DEPTH;

    const float* dbase = disp + (size_t)b * HW;
    const float* imb   = img  + (size_t)b * CH * HW;
    float* outb        = out  + (size_t)b * CH * HW;

    const int gidx0 = (yt + rp) * W + x;

    // ---- Phase 1: all disp loads (independent, overlapped) ----
    float dval[RPT];
#pragma unroll
    for (int k = 0; k < RPT; k++)
        dval[k] = __ldg(dbase + gidx0 + k * 2 * W);

    // ---- Phase 2: all coordinates / weights / tap offsets ----
    int   o00[RPT], odx[RPT], ody[RPT];
    float w00[RPT], w01[RPT], w10[RPT], w11[RPT];
    const float fy0 = (float)(yt + rp);
    float ay_x = m1 * fy0 + tx_x;  const float sy_x = 2.0f * m1;
    float ay_y = m4 * fy0 + tx_y;  const float sy_y = 2.0f * m4;
    float ay_z = m7 * fy0 + tx_z;  const float sy_z = 2.0f * m7;

#pragma unroll
    for (int k = 0; k < RPT; k++) {
        float s  = fmaf(drange, dval[k], min_disp);     // scaled disparity = 1/depth
        float nx = fmaf(c0,  s, ay_x);                  // scaled numerators
        float ny = fmaf(c1,  s, ay_y);
        float dz = fmaf(c2e, s, ay_z);                  // denom (eps folded)
        ay_x += sy_x; ay_y += sy_y; ay_z += sy_z;

        float rz = __fdividef(1.0f, dz);                // the ONLY division
        float xf = fmaf(nx, rz, -0.5f);
        float yf = fmaf(ny, rz, -0.5f);

        int ix0 = __float2int_rd(xf);
        int iy0 = __float2int_rd(yf);
        float wx = xf - (float)ix0;
        float wy = yf - (float)iy0;

        if (INTERIOR) {
            // warp-field bounds proven: ix0 in [x-1,x], iy0 in [y-1,y]; tile interior
            o00[k] = iy0 * W + ix0;
            odx[k] = 1;
            ody[k] = W;
        } else {
            int ix1 = min(max(ix0 + 1, 0), W - 1);
            int iy1 = min(max(iy0 + 1, 0), H - 1);
            ix0 = min(max(ix0, 0), W - 1);
            iy0 = min(max(iy0, 0), H - 1);
            o00[k] = iy0 * W + ix0;
            odx[k] = ix1 - ix0;
            ody[k] = (iy1 - iy0) * W;
        }

        float iwx = 1.0f - wx;
        float iwy = 1.0f - wy;
        w00[k] = iwx * iwy;
        w01[k] = wx * iwy;
        w10[k] = iwx * wy;
        w11[k] = wx * wy;
    }

    // ---- Phase 3: all gathers (channel offsets folded as LDG immediates) ----
    float t00[RPT][CH], t01[RPT][CH], t10[RPT][CH], t11[RPT][CH];
#pragma unroll
    for (int k = 0; k < RPT; k++) {
        const float* p00 = imb + o00[k];
        const float* p01 = p00 + odx[k];
        const float* p10 = p00 + ody[k];
        const float* p11 = p10 + odx[k];
#pragma unroll
        for (int ch = 0; ch < CH; ch++) {
            t00[k][ch] = __ldg(p00 + ch * HW);
            t01[k][ch] = __ldg(p01 + ch * HW);
            t10[k][ch] = __ldg(p10 + ch * HW);
            t11[k][ch] = __ldg(p11 + ch * HW);
        }
    }

    // ---- Phase 4: blend + store ----
#pragma unroll
    for (int k = 0; k < RPT; k++) {
        const int gidx = gidx0 + k * 2 * W;
#pragma unroll
        for (int ch = 0; ch < CH; ch++) {
            float v = t00[k][ch] * w00[k];
            v = fmaf(t01[k][ch], w01[k], v);
            v = fmaf(t10[k][ch], w10[k], v);
            v = fmaf(t11[k][ch], w11[k], v);
            outb[ch * HW + gidx] = v;
        }
    }
}

// Single fused kernel: lanes 0-11 compute fused projection params in-kernel,
// with grid-scale constants folded in:
//   rows 0 (and c0) scaled by W/(W-1); rows 1 (and c1) by H/(H-1); c2 += EPS.
__global__ __launch_bounds__(256) void synth_kernel(const float* __restrict__ img,
                                                    const float* __restrict__ disp,
                                                    const float* __restrict__ srcK,
                                                    const float* __restrict__ tgtK,
                                                    const float* __restrict__ tvec,
                                                    float* __restrict__ out) {
    __shared__ float sP[12];

    const int b  = blockIdx.z;
    const int yt = blockIdx.y * TILE_H;
    const int xt = blockIdx.x * TILE_W;
    const int tid = threadIdx.x;

    if (tid < 12) {
        const float* S = srcK + b * 16;
        const float* T = tgtK + b * 16;
        const float* t = tvec + b * 3;

        float a00 = __ldg(S + 0), a01 = __ldg(S + 1), a02 = __ldg(S + 2);
        float a10 = __ldg(S + 4), a11 = __ldg(S + 5), a12 = __ldg(S + 6);
        float a20 = __ldg(S + 8), a21 = __ldg(S + 9), a22 = __ldg(S + 10);
        float ad00 = a11 * a22 - a12 * a21;
        float ad01 = a02 * a21 - a01 * a22;
        float ad02 = a01 * a12 - a02 * a11;
        float ad10 = a12 * a20 - a10 * a22;
        float ad11 = a00 * a22 - a02 * a20;
        float ad12 = a02 * a10 - a00 * a12;
        float ad20 = a10 * a21 - a11 * a20;
        float ad21 = a01 * a20 - a00 * a21;
        float ad22 = a00 * a11 - a01 * a10;
        float id = 1.0f / (a00 * ad00 + a01 * ad10 + a02 * ad20);

        int r = (tid < 9) ? (tid / 3) : (tid - 9);
        float T0 = __ldg(T + r * 4 + 0);
        float T1 = __ldg(T + r * 4 + 1);
        float T2 = __ldg(T + r * 4 + 2);

        float val;
        if (tid < 9) {
            int c = tid - r * 3;
            float A0 = (c == 0) ? ad00 : (c == 1) ? ad01 : ad02;
            float A1 = (c == 0) ? ad10 : (c == 1) ? ad11 : ad12;
            float A2 = (c == 0) ? ad20 : (c == 1) ? ad21 : ad22;
            val = (T0 * A0 + T1 * A1 + T2 * A2) * id;
        } else {
            val = T0 * __ldg(t + 0) + T1 * __ldg(t + 1) + T2 * __ldg(t + 2);
        }

        // fold grid-scale constants
        const float SXW = (float)W / (float)(W - 1);
        const float SYH = (float)H / (float)(H - 1);
        if (r == 0)       val *= SXW;    // x row and c0
        else if (r == 1)  val *= SYH;    // y row and c1
        else if (tid == 11) val += EPS;  // c2 + eps (z row m6..m8 unscaled)
        sP[tid] = val;
    }
    __syncthreads();

    const bool interior = (blockIdx.x > 0) & (blockIdx.x < gridDim.x - 1)
                        & (blockIdx.y > 0) & (blockIdx.y < gridDim.y - 1);
    if (interior)
        synth_body<true>(img, disp, out, sP, b, yt, xt, tid);
    else
        synth_body<false>(img, disp, out, sP, b, yt, xt, tid);
}

extern "C" void kernel_launch(void* const* d_in, const int* in_sizes, int n_in,
                              void* d_out, int out_size) {
    const float* img  = (const float*)d_in[0];
    const float* disp = (const float*)d_in[1];
    const float* srcK = (const float*)d_in[2];
    const float* tgtK = (const float*)d_in[3];
    const float* tvec = (const float*)d_in[4];
    float* out = (float*)d_out;

    dim3 grid(W / TILE_W, H / TILE_H, BATCH);   // (10, 128, 8)
    synth_kernel<<<grid, 256>>>(img, disp, srcK, tgtK, tvec, out);
}

// round 12
// speedup vs baseline: 1.1445x; 1.0151x over previous
#include <cuda_runtime.h>

#define BATCH 8
#define CH 3
#define H 1024
#define W 1280
#define HW (H * W)
#define EPS 1e-7f
#define MIN_DEPTH 10.0f
#define MAX_DEPTH 255.0f

#define TILE_W 128
#define TILE_H 8
#define RPT 4                 // rows per thread

// Phase-batched body; single-division projection (grid scales prefolded).
// Phase 3 uses tap-major (miss-first) ordering.
template <bool INTERIOR>
__device__ __forceinline__ void synth_body(const float* __restrict__ img,
                                           const float* __restrict__ disp,
                                           float* __restrict__ out,
                                           const float* sP,
                                           int b, int yt, int xt, int tid) {
    const float m1 = sP[1], m4 = sP[4], m7 = sP[7];
    const float c0 = sP[9], c1 = sP[10], c2e = sP[11];

    const int lx = tid & (TILE_W - 1);   // adjacent lanes -> adjacent x
    const int rp = tid >> 7;             // 0 or 1
    const int x  = xt + lx;
    const float fx = (float)x;

    const float tx_x = sP[0] * fx + sP[2];
    const float tx_y = sP[3] * fx + sP[5];
    const float tx_z = sP[6] * fx + sP[8];

    const float min_disp = 1.0f / MAX_DEPTH;
    const float drange   = 1.0f / MIN_DEPTH - 1.0f / MAX_DEPTH;

    const float* dbase = disp + (size_t)b * HW;
    const float* imb   = img  + (size_t)b * CH * HW;
    float* outb        = out  + (size_t)b * CH * HW;

    const int gidx0 = (yt + rp) * W + x;

    // ---- Phase 1: all disp loads (independent, overlapped) ----
    float dval[RPT];
#pragma unroll
    for (int k = 0; k < RPT; k++)
        dval[k] = __ldg(dbase + gidx0 + k * 2 * W);

    // ---- Phase 2: all coordinates / weights / tap offsets ----
    int   o00[RPT], odx[RPT], ody[RPT];
    float w00[RPT], w01[RPT], w10[RPT], w11[RPT];
    const float fy0 = (float)(yt + rp);
    float ay_x = m1 * fy0 + tx_x;  const float sy_x = 2.0f * m1;
    float ay_y = m4 * fy0 + tx_y;  const float sy_y = 2.0f * m4;
    float ay_z = m7 * fy0 + tx_z;  const float sy_z = 2.0f * m7;

#pragma unroll
    for (int k = 0; k < RPT; k++) {
        float s  = fmaf(drange, dval[k], min_disp);     // 1/depth
        float nx = fmaf(c0,  s, ay_x);
        float ny = fmaf(c1,  s, ay_y);
        float dz = fmaf(c2e, s, ay_z);
        ay_x += sy_x; ay_y += sy_y; ay_z += sy_z;

        float rz = __fdividef(1.0f, dz);                // the ONLY division
        float xf = fmaf(nx, rz, -0.5f);
        float yf = fmaf(ny, rz, -0.5f);

        int ix0 = __float2int_rd(xf);
        int iy0 = __float2int_rd(yf);
        float wx = xf - (float)ix0;
        float wy = yf - (float)iy0;

        if (INTERIOR) {
            o00[k] = iy0 * W + ix0;
            odx[k] = 1;
            ody[k] = W;
        } else {
            int ix1 = min(max(ix0 + 1, 0), W - 1);
            int iy1 = min(max(iy0 + 1, 0), H - 1);
            ix0 = min(max(ix0, 0), W - 1);
            iy0 = min(max(iy0, 0), H - 1);
            o00[k] = iy0 * W + ix0;
            odx[k] = ix1 - ix0;
            ody[k] = (iy1 - iy0) * W;
        }

        float iwx = 1.0f - wx;
        float iwy = 1.0f - wy;
        w00[k] = iwx * iwy;
        w01[k] = wx * iwy;
        w10[k] = iwx * wy;
        w11[k] = wx * wy;
    }

    // ---- Phase 3: tap-major (miss-first) gathers ----
    float t00[RPT][CH], t01[RPT][CH], t10[RPT][CH], t11[RPT][CH];
    // wave 1: top-left taps — all distinct line groups (misses) first
#pragma unroll
    for (int k = 0; k < RPT; k++) {
        const float* p00 = imb + o00[k];
#pragma unroll
        for (int ch = 0; ch < CH; ch++)
            t00[k][ch] = __ldg(p00 + ch * HW);
    }
    // wave 2: bottom-left taps — next row's distinct lines (misses)
#pragma unroll
    for (int k = 0; k < RPT; k++) {
        const float* p10 = imb + o00[k] + ody[k];
#pragma unroll
        for (int ch = 0; ch < CH; ch++)
            t10[k][ch] = __ldg(p10 + ch * HW);
    }
    // waves 3-4: right taps — same lines as waves 1-2 (hits)
#pragma unroll
    for (int k = 0; k < RPT; k++) {
        const float* p01 = imb + o00[k] + odx[k];
#pragma unroll
        for (int ch = 0; ch < CH; ch++)
            t01[k][ch] = __ldg(p01 + ch * HW);
    }
#pragma unroll
    for (int k = 0; k < RPT; k++) {
        const float* p11 = imb + o00[k] + ody[k] + odx[k];
#pragma unroll
        for (int ch = 0; ch < CH; ch++)
            t11[k][ch] = __ldg(p11 + ch * HW);
    }

    // ---- Phase 4: blend + store ----
#pragma unroll
    for (int k = 0; k < RPT; k++) {
        const int gidx = gidx0 + k * 2 * W;
#pragma unroll
        for (int ch = 0; ch < CH; ch++) {
            float v = t00[k][ch] * w00[k];
            v = fmaf(t01[k][ch], w01[k], v);
            v = fmaf(t10[k][ch], w10[k], v);
            v = fmaf(t11[k][ch], w11[k], v);
            outb[ch * HW + gidx] = v;
        }
    }
}

// Single fused kernel: lanes 0-11 compute fused projection params in-kernel.
__global__ __launch_bounds__(256, 6) void synth_kernel(const float* __restrict__ img,
                                                       const float* __restrict__ disp,
                                                       const float* __restrict__ srcK,
                                                       const float* __restrict__ tgtK,
                                                       const float* __restrict__ tvec,
                                                       float* __restrict__ out) {
    __shared__ float sP[12];

    const int b  = blockIdx.z;
    const int yt = blockIdx.y * TILE_H;
    const int xt = blockIdx.x * TILE_W;
    const int tid = threadIdx.x;

    if (tid < 12) {
        const float* S = srcK + b * 16;
        const float* T = tgtK + b * 16;
        const float* t = tvec + b * 3;

        float a00 = __ldg(S + 0), a01 = __ldg(S + 1), a02 = __ldg(S + 2);
        float a10 = __ldg(S + 4), a11 = __ldg(S + 5), a12 = __ldg(S + 6);
        float a20 = __ldg(S + 8), a21 = __ldg(S + 9), a22 = __ldg(S + 10);
        float ad00 = a11 * a22 - a12 * a21;
        float ad01 = a02 * a21 - a01 * a22;
        float ad02 = a01 * a12 - a02 * a11;
        float ad10 = a12 * a20 - a10 * a22;
        float ad11 = a00 * a22 - a02 * a20;
        float ad12 = a02 * a10 - a00 * a12;
        float ad20 = a10 * a21 - a11 * a20;
        float ad21 = a01 * a20 - a00 * a21;
        float ad22 = a00 * a11 - a01 * a10;
        float id = 1.0f / (a00 * ad00 + a01 * ad10 + a02 * ad20);

        int r = (tid < 9) ? (tid / 3) : (tid - 9);
        float T0 = __ldg(T + r * 4 + 0);
        float T1 = __ldg(T + r * 4 + 1);
        float T2 = __ldg(T + r * 4 + 2);

        float val;
        if (tid < 9) {
            int c = tid - r * 3;
            float A0 = (c == 0) ? ad00 : (c == 1) ? ad01 : ad02;
            float A1 = (c == 0) ? ad10 : (c == 1) ? ad11 : ad12;
            float A2 = (c == 0) ? ad20 : (c == 1) ? ad21 : ad22;
            val = (T0 * A0 + T1 * A1 + T2 * A2) * id;
        } else {
            val = T0 * __ldg(t + 0) + T1 * __ldg(t + 1) + T2 * __ldg(t + 2);
        }

        const float SXW = (float)W / (float)(W - 1);
        const float SYH = (float)H / (float)(H - 1);
        if (r == 0)        val *= SXW;
        else if (r == 1)   val *= SYH;
        else if (tid == 11) val += EPS;
        sP[tid] = val;
    }
    __syncthreads();

    const bool interior = (blockIdx.x > 0) & (blockIdx.x < gridDim.x - 1)
                        & (blockIdx.y > 0) & (blockIdx.y < gridDim.y - 1);
    if (interior)
        synth_body<true>(img, disp, out, sP, b, yt, xt, tid);
    else
        synth_body<false>(img, disp, out, sP, b, yt, xt, tid);
}

extern "C" void kernel_launch(void* const* d_in, const int* in_sizes, int n_in,
                              void* d_out, int out_size) {
    const float* img  = (const float*)d_in[0];
    const float* disp = (const float*)d_in[1];
    const float* srcK = (const float*)d_in[2];
    const float* tgtK = (const float*)d_in[3];
    const float* tvec = (const float*)d_in[4];
    float* out = (float*)d_out;

    dim3 grid(W / TILE_W, H / TILE_H, BATCH);   // (10, 128, 8)
    synth_kernel<<<grid, 256>>>(img, disp, srcK, tgtK, tvec, out);
}

// round 13
// speedup vs baseline: 1.2670x; 1.1070x over previous
#include <cuda_runtime.h>

#define BATCH 8
#define CH 3
#define H 1024
#define W 1280
#define HW (H * W)
#define EPS 1e-7f
#define MIN_DEPTH 10.0f
#define MAX_DEPTH 255.0f

#define TILE_W 128
#define TILE_H 8
#define RPT 4                 // rows per thread

// Phase-batched body; single-division projection (grid scales prefolded).
// Phase 3 uses tap-major (miss-first) ordering.
template <bool INTERIOR>
__device__ __forceinline__ void synth_body(const float* __restrict__ img,
                                           const float* __restrict__ disp,
                                           float* __restrict__ out,
                                           const float* sP,
                                           int b, int yt, int xt, int tid) {
    const float m1 = sP[1], m4 = sP[4], m7 = sP[7];
    const float c0 = sP[9], c1 = sP[10], c2e = sP[11];

    const int lx = tid & (TILE_W - 1);   // adjacent lanes -> adjacent x
    const int rp = tid >> 7;             // 0 or 1
    const int x  = xt + lx;
    const float fx = (float)x;

    const float tx_x = sP[0] * fx + sP[2];
    const float tx_y = sP[3] * fx + sP[5];
    const float tx_z = sP[6] * fx + sP[8];

    const float min_disp = 1.0f / MAX_DEPTH;
    const float drange   = 1.0f / MIN_DEPTH - 1.0f / MAX_DEPTH;

    const float* dbase = disp + (size_t)b * HW;
    const float* imb   = img  + (size_t)b * CH * HW;
    float* outb        = out  + (size_t)b * CH * HW;

    const int gidx0 = (yt + rp) * W + x;

    // ---- Phase 1: all disp loads (independent, overlapped) ----
    float dval[RPT];
#pragma unroll
    for (int k = 0; k < RPT; k++)
        dval[k] = __ldg(dbase + gidx0 + k * 2 * W);

    // ---- Phase 2: all coordinates / weights / tap offsets ----
    int   o00[RPT], odx[RPT], ody[RPT];
    float w00[RPT], w01[RPT], w10[RPT], w11[RPT];
    const float fy0 = (float)(yt + rp);
    float ay_x = m1 * fy0 + tx_x;  const float sy_x = 2.0f * m1;
    float ay_y = m4 * fy0 + tx_y;  const float sy_y = 2.0f * m4;
    float ay_z = m7 * fy0 + tx_z;  const float sy_z = 2.0f * m7;

#pragma unroll
    for (int k = 0; k < RPT; k++) {
        float s  = fmaf(drange, dval[k], min_disp);     // 1/depth
        float nx = fmaf(c0,  s, ay_x);
        float ny = fmaf(c1,  s, ay_y);
        float dz = fmaf(c2e, s, ay_z);
        ay_x += sy_x; ay_y += sy_y; ay_z += sy_z;

        float rz = __fdividef(1.0f, dz);                // the ONLY division
        float xf = fmaf(nx, rz, -0.5f);
        float yf = fmaf(ny, rz, -0.5f);

        int ix0 = __float2int_rd(xf);
        int iy0 = __float2int_rd(yf);
        float wx = xf - (float)ix0;
        float wy = yf - (float)iy0;

        if (INTERIOR) {
            o00[k] = iy0 * W + ix0;
            odx[k] = 1;
            ody[k] = W;
        } else {
            int ix1 = min(max(ix0 + 1, 0), W - 1);
            int iy1 = min(max(iy0 + 1, 0), H - 1);
            ix0 = min(max(ix0, 0), W - 1);
            iy0 = min(max(iy0, 0), H - 1);
            o00[k] = iy0 * W + ix0;
            odx[k] = ix1 - ix0;
            ody[k] = (iy1 - iy0) * W;
        }

        float iwx = 1.0f - wx;
        float iwy = 1.0f - wy;
        w00[k] = iwx * iwy;
        w01[k] = wx * iwy;
        w10[k] = iwx * wy;
        w11[k] = wx * wy;
    }

    // ---- Phase 3: tap-major (miss-first) gathers ----
    float t00[RPT][CH], t01[RPT][CH], t10[RPT][CH], t11[RPT][CH];
#pragma unroll
    for (int k = 0; k < RPT; k++) {
        const float* p00 = imb + o00[k];
#pragma unroll
        for (int ch = 0; ch < CH; ch++)
            t00[k][ch] = __ldg(p00 + ch * HW);
    }
#pragma unroll
    for (int k = 0; k < RPT; k++) {
        const float* p10 = imb + o00[k] + ody[k];
#pragma unroll
        for (int ch = 0; ch < CH; ch++)
            t10[k][ch] = __ldg(p10 + ch * HW);
    }
#pragma unroll
    for (int k = 0; k < RPT; k++) {
        const float* p01 = imb + o00[k] + odx[k];
#pragma unroll
        for (int ch = 0; ch < CH; ch++)
            t01[k][ch] = __ldg(p01 + ch * HW);
    }
#pragma unroll
    for (int k = 0; k < RPT; k++) {
        const float* p11 = imb + o00[k] + ody[k] + odx[k];
#pragma unroll
        for (int ch = 0; ch < CH; ch++)
            t11[k][ch] = __ldg(p11 + ch * HW);
    }

    // ---- Phase 4: blend + store ----
#pragma unroll
    for (int k = 0; k < RPT; k++) {
        const int gidx = gidx0 + k * 2 * W;
#pragma unroll
        for (int ch = 0; ch < CH; ch++) {
            float v = t00[k][ch] * w00[k];
            v = fmaf(t01[k][ch], w01[k], v);
            v = fmaf(t10[k][ch], w10[k], v);
            v = fmaf(t11[k][ch], w11[k], v);
            outb[ch * HW + gidx] = v;
        }
    }
}

// Single fused kernel: L2 prefetch of img tile up front; lanes 0-11 compute
// fused projection params; then phase-batched body.
__global__ __launch_bounds__(256, 6) void synth_kernel(const float* __restrict__ img,
                                                       const float* __restrict__ disp,
                                                       const float* __restrict__ srcK,
                                                       const float* __restrict__ tgtK,
                                                       const float* __restrict__ tvec,
                                                       float* __restrict__ out) {
    __shared__ float sP[12];

    const int b  = blockIdx.z;
    const int yt = blockIdx.y * TILE_H;
    const int xt = blockIdx.x * TILE_W;
    const int tid = threadIdx.x;

    // ---- L2 prefetch of the img tile this block will gather from ----
    // rows [yt-1, yt+8] clamped, a 136-col window clamped, 3 channels.
    // 10 rows x 3 ch x 6 lines = 180 prefetches, one per thread (tid < 180).
    {
        const float* imb = img + (size_t)b * CH * HW;
        if (tid < 180) {
            int ch = tid / 60;               // 0..2
            int r6 = tid - ch * 60;          // 0..59
            int r  = r6 / 6;                 // row 0..9
            int l  = r6 - r * 6;             // line 0..5
            int gy = min(max(yt - 1 + r, 0), H - 1);
            int gc = min(max(xt - 2, 0), W - 136);   // clamped 136-col window
            const char* base = (const char*)(imb + ch * HW + gy * W + gc);
            const char* linep = (const char*)((size_t)base & ~(size_t)127) + l * 128;
            asm volatile("prefetch.global.L2 [%0];" :: "l"(linep));
        }
    }

    if (tid < 12) {
        const float* S = srcK + b * 16;
        const float* T = tgtK + b * 16;
        const float* t = tvec + b * 3;

        float a00 = __ldg(S + 0), a01 = __ldg(S + 1), a02 = __ldg(S + 2);
        float a10 = __ldg(S + 4), a11 = __ldg(S + 5), a12 = __ldg(S + 6);
        float a20 = __ldg(S + 8), a21 = __ldg(S + 9), a22 = __ldg(S + 10);
        float ad00 = a11 * a22 - a12 * a21;
        float ad01 = a02 * a21 - a01 * a22;
        float ad02 = a01 * a12 - a02 * a11;
        float ad10 = a12 * a20 - a10 * a22;
        float ad11 = a00 * a22 - a02 * a20;
        float ad12 = a02 * a10 - a00 * a12;
        float ad20 = a10 * a21 - a11 * a20;
        float ad21 = a01 * a20 - a00 * a21;
        float ad22 = a00 * a11 - a01 * a10;
        float id = 1.0f / (a00 * ad00 + a01 * ad10 + a02 * ad20);

        int r = (tid < 9) ? (tid / 3) : (tid - 9);
        float T0 = __ldg(T + r * 4 + 0);
        float T1 = __ldg(T + r * 4 + 1);
        float T2 = __ldg(T + r * 4 + 2);

        float val;
        if (tid < 9) {
            int c = tid - r * 3;
            float A0 = (c == 0) ? ad00 : (c == 1) ? ad01 : ad02;
            float A1 = (c == 0) ? ad10 : (c == 1) ? ad11 : ad12;
            float A2 = (c == 0) ? ad20 : (c == 1) ? ad21 : ad22;
            val = (T0 * A0 + T1 * A1 + T2 * A2) * id;
        } else {
            val = T0 * __ldg(t + 0) + T1 * __ldg(t + 1) + T2 * __ldg(t + 2);
        }

        const float SXW = (float)W / (float)(W - 1);
        const float SYH = (float)H / (float)(H - 1);
        if (r == 0)        val *= SXW;
        else if (r == 1)   val *= SYH;
        else if (tid == 11) val += EPS;
        sP[tid] = val;
    }
    __syncthreads();

    const bool interior = (blockIdx.x > 0) & (blockIdx.x < gridDim.x - 1)
                        & (blockIdx.y > 0) & (blockIdx.y < gridDim.y - 1);
    if (interior)
        synth_body<true>(img, disp, out, sP, b, yt, xt, tid);
    else
        synth_body<false>(img, disp, out, sP, b, yt, xt, tid);
}

extern "C" void kernel_launch(void* const* d_in, const int* in_sizes, int n_in,
                              void* d_out, int out_size) {
    const float* img  = (const float*)d_in[0];
    const float* disp = (const float*)d_in[1];
    const float* srcK = (const float*)d_in[2];
    const float* tgtK = (const float*)d_in[3];
    const float* tvec = (const float*)d_in[4];
    float* out = (float*)d_out;

    dim3 grid(W / TILE_W, H / TILE_H, BATCH);   // (10, 128, 8)
    synth_kernel<<<grid, 256>>>(img, disp, srcK, tgtK, tvec, out);
}